// round 11
// baseline (speedup 1.0000x reference)
#include <cuda_runtime.h>
#include <cuda_bf16.h>
#include <cstdint>

#define NUM_CLASSES 100000
#define EMBED 512
#define BATCH_N 4096
#define LAMBDA_C 0.01f
#define ALPHA_C 0.1f

#define NCS ((size_t)NUM_CLASSES * EMBED)   // 51,200,000 floats
#define GRID (NUM_CLASSES / 2)               // 50,000 blocks, 2 rows each
#define BUILD_BLOCKS (BATCH_N / 256)         // 16

// All zero-initialized at module load; every call restores zeros before exit,
// so the invariant holds across graph replays (no memset pass needed).
// g_head[c]: 0 = untouched, i+1 = sample i heads class c's chain.
__device__ int g_head[NUM_CLASSES];
__device__ int g_next[BATCH_N];
__device__ unsigned g_build_done;
__device__ unsigned g_pass;
__device__ float g_loss;

__device__ __forceinline__ void st_cs4(float* p, float4 v) {
    asm volatile("st.global.cs.v4.f32 [%0], {%1,%2,%3,%4};"
                 :: "l"(p), "f"(v.x), "f"(v.y), "f"(v.z), "f"(v.w) : "memory");
}

__global__ __launch_bounds__(256)
void mega_kernel(const int* __restrict__ y,
                 const float* __restrict__ src,      // centers (scalar view)
                 const float4* __restrict__ src4,    // centers (float4 view)
                 const float4* __restrict__ batch4,
                 float* __restrict__ dst,            // new_centers (= out+1)
                 float* __restrict__ loss_out) {
    const int tid = threadIdx.x;
    const int bid = blockIdx.x;

    // ---- Phase A: build chains (first 16 blocks; wave-1 residents) ----
    if (bid < BUILD_BLOCKS) {
        const int i = bid * 256 + tid;              // covers all 4096 samples
        const int c = y[i];
        const int old = atomicExch(&g_head[c], i + 1);
        g_next[i] = old;
        __threadfence();                            // release chain writes
        __syncthreads();
        if (tid == 0) atomicAdd(&g_build_done, 1u);
    }

    // ---- Phase B: unconditional streaming copy (aligned interior) ----
    const int row = bid * 2 + (tid >> 7);
    const int t   = tid & 127;
    const size_t rbase = (size_t)row * EMBED;

    if (t < 127) {
        // dst elems rbase+3+4t .. +6+4t  (16B-aligned since dst = out+1)
        float4 A = __ldcs(src4 + (size_t)row * 128 + t + 1); // elems 4+4t..7+4t
        float  s = __ldcs(src + rbase + 3 + 4 * t);          // straddler
        st_cs4(dst + rbase + 3 + 4 * t, make_float4(s, A.x, A.y, A.z));
    } else {
        // row edges: elems 0,1,2 and 511
        float e0 = __ldcs(src + rbase + 0);
        float e1 = __ldcs(src + rbase + 1);
        float e2 = __ldcs(src + rbase + 2);
        float e511 = __ldcs(src + rbase + 511);
        dst[rbase + 0] = e0;
        dst[rbase + 1] = e1;
        dst[rbase + 2] = e2;
        dst[rbase + 511] = e511;
    }

    // ---- Phase C: gate on build completion ----
    if (tid == 0) {
        while (*(volatile unsigned*)&g_build_done < (unsigned)BUILD_BLOCKS)
            __nanosleep(64);
        __threadfence();                            // acquire
    }
    __syncthreads();  // also orders Phase-B stores before Phase-D overwrite

    // ---- Phase D: rare overwrite of touched rows + loss ----
    const int h = __ldcg(&g_head[row]);             // half-block uniform
    if (h > 0) {
        float4 c4 = src4[(size_t)row * 128 + t];
        float ax = 0.f, ay = 0.f, az = 0.f, aw = 0.f, ls = 0.f;
        int s = h;
        while (s > 0) {
            float4 b4 = batch4[(size_t)(s - 1) * (EMBED / 4) + t];
            float dx = b4.x - c4.x;
            float dy = b4.y - c4.y;
            float dz = b4.z - c4.z;
            float dw = b4.w - c4.w;
            ax += dx; ay += dy; az += dz; aw += dw;
            ls += dx * dx + dy * dy + dz * dz + dw * dw;
            s = g_next[s - 1];
        }
        // sole logical writer after the gate syncthreads; overwrite copy
        float* d = dst + rbase + 4 * t;             // misaligned: scalars
        d[0] = c4.x + ALPHA_C * ax;
        d[1] = c4.y + ALPHA_C * ay;
        d[2] = c4.z + ALPHA_C * az;
        d[3] = c4.w + ALPHA_C * aw;

        #pragma unroll
        for (int off = 16; off > 0; off >>= 1)
            ls += __shfl_xor_sync(0xFFFFFFFFu, ls, off);
        if ((t & 31) == 0)
            atomicAdd(&g_loss, ls);                 // raw sum; scaled at end

        if (t == 0) g_head[row] = 0;                // restore zero-invariant
    }

    // ---- Phase E: last block publishes loss and resets globals ----
    __syncthreads();
    if (tid == 0) {
        __threadfence();                            // release g_loss adds
        unsigned n = atomicAdd(&g_pass, 1u);
        if (n == (unsigned)(GRID - 1)) {
            __threadfence();                        // acquire all g_loss adds
            float tot = *(volatile float*)&g_loss;
            loss_out[0] = tot * (LAMBDA_C / (float)BATCH_N);
            g_loss = 0.0f;
            g_pass = 0u;
            g_build_done = 0u;
        }
    }
}

extern "C" void kernel_launch(void* const* d_in, const int* in_sizes, int n_in,
                              void* d_out, int out_size) {
    const int*   y       = (const int*)d_in[0];
    const float* batch   = (const float*)d_in[1];
    const float* centers = (const float*)d_in[2];

    float* out = (float*)d_out;

    float* loss_ptr;
    float* new_centers;
    if (out_size == (int)(NCS + 1)) {
        loss_ptr = out;
        new_centers = out + 1;
    } else {
        new_centers = out;
        loss_ptr = out + NCS;
    }

    mega_kernel<<<GRID, 256>>>(y, centers,
        reinterpret_cast<const float4*>(centers),
        reinterpret_cast<const float4*>(batch),
        new_centers, loss_ptr);
}

// round 12
// speedup vs baseline: 1.5930x; 1.5930x over previous
#include <cuda_runtime.h>
#include <cuda_bf16.h>
#include <cstdint>

#define NUM_CLASSES 100000
#define EMBED 512
#define BATCH_N 4096
#define LAMBDA_C 0.01f
#define ALPHA_C 0.1f

#define NCS ((size_t)NUM_CLASSES * EMBED)   // 51,200,000 floats
#define N4  (NCS / 4)                        // 12,800,000 float4s
#define COPY_GRID ((unsigned)(N4 / 256))     // 50,000 blocks

// Zero-initialized at load; fixup restores zeros, so the invariant holds
// across calls/replays. g_head[c]: 0 = untouched, i+1 = sample i is head.
__device__ int g_head[NUM_CLASSES];
__device__ int g_next[BATCH_N];

// Kernel 1: pure streaming copy (R2-proven hot path). Blocks 0-15 ALSO build
// the chains first (no one reads g_head in this kernel -> no gating needed;
// the stream-ordered fixup kernel is the only consumer). Block 16 zeroes loss.
__global__ __launch_bounds__(256)
void copy_build_kernel(const float4* __restrict__ src,
                       float* __restrict__ dst,
                       const int* __restrict__ y,
                       float* __restrict__ loss) {
    const int bid = blockIdx.x;
    const int tid = threadIdx.x;

    if (bid < 16) {                              // build: 16*256 = 4096 samples
        const int i = bid * 256 + tid;
        const int c = y[i];
        const int old = atomicExch(&g_head[c], i + 1);
        g_next[i] = old;
    } else if (bid == 16 && tid == 0) {
        *loss = 0.0f;
    }

    // unconditional copy: aligned LDG.128 + 4x scalar STG.32 (dst = out+1)
    const size_t q = (size_t)bid * 256 + tid;
    float4 v = __ldcs(src + q);
    float* d = dst + q * 4;
    __stcs(d + 0, v.x);
    __stcs(d + 1, v.y);
    __stcs(d + 2, v.z);
    __stcs(d + 3, v.w);
}

// Kernel 2: fixup, one WARP per sample (4096 warps = 512 blocks x 256).
// Every warp adds its sample's loss term; the chain-head warp overwrites the
// touched row (sole writer per class) and restores g_head[c] = 0.
__global__ __launch_bounds__(256)
void fixup_kernel(const int* __restrict__ y,
                  const float4* __restrict__ batch4,
                  const float4* __restrict__ centers4,
                  float* __restrict__ dst,
                  float* __restrict__ loss) {
    const int gw   = (blockIdx.x * 256 + threadIdx.x) >> 5;  // warp id = sample
    const int lane = threadIdx.x & 31;
    const int i = gw;
    const int c = __ldg(y + i);                 // broadcast within warp

    const size_t crow = (size_t)c * (EMBED / 4);
    const size_t brow = (size_t)i * (EMBED / 4);

    // 4 float4s per lane: indices lane, lane+32, lane+64, lane+96
    float4 c0 = centers4[crow + lane];
    float4 c1 = centers4[crow + lane + 32];
    float4 c2 = centers4[crow + lane + 64];
    float4 c3 = centers4[crow + lane + 96];
    float4 b0 = batch4[brow + lane];
    float4 b1 = batch4[brow + lane + 32];
    float4 b2 = batch4[brow + lane + 64];
    float4 b3 = batch4[brow + lane + 96];

    float d0x = b0.x - c0.x, d0y = b0.y - c0.y, d0z = b0.z - c0.z, d0w = b0.w - c0.w;
    float d1x = b1.x - c1.x, d1y = b1.y - c1.y, d1z = b1.z - c1.z, d1w = b1.w - c1.w;
    float d2x = b2.x - c2.x, d2y = b2.y - c2.y, d2z = b2.z - c2.z, d2w = b2.w - c2.w;
    float d3x = b3.x - c3.x, d3y = b3.y - c3.y, d3z = b3.z - c3.z, d3w = b3.w - c3.w;

    // own loss term
    float ls = d0x*d0x + d0y*d0y + d0z*d0z + d0w*d0w
             + d1x*d1x + d1y*d1y + d1z*d1z + d1w*d1w
             + d2x*d2x + d2y*d2y + d2z*d2z + d2w*d2w
             + d3x*d3x + d3y*d3y + d3z*d3z + d3w*d3w;
    #pragma unroll
    for (int off = 16; off > 0; off >>= 1)
        ls += __shfl_xor_sync(0xFFFFFFFFu, ls, off);
    if (lane == 0)
        atomicAdd(loss, ls * (LAMBDA_C / (float)BATCH_N));

    // chain head overwrites the row
    if (__ldg(&g_head[c]) == i + 1) {
        float ax0 = d0x, ay0 = d0y, az0 = d0z, aw0 = d0w;
        float ax1 = d1x, ay1 = d1y, az1 = d1z, aw1 = d1w;
        float ax2 = d2x, ay2 = d2y, az2 = d2z, aw2 = d2w;
        float ax3 = d3x, ay3 = d3y, az3 = d3z, aw3 = d3w;
        int s = g_next[i];
        while (s > 0) {
            const size_t qrow = (size_t)(s - 1) * (EMBED / 4);
            float4 q0 = batch4[qrow + lane];
            float4 q1 = batch4[qrow + lane + 32];
            float4 q2 = batch4[qrow + lane + 64];
            float4 q3 = batch4[qrow + lane + 96];
            ax0 += q0.x - c0.x; ay0 += q0.y - c0.y; az0 += q0.z - c0.z; aw0 += q0.w - c0.w;
            ax1 += q1.x - c1.x; ay1 += q1.y - c1.y; az1 += q1.z - c1.z; aw1 += q1.w - c1.w;
            ax2 += q2.x - c2.x; ay2 += q2.y - c2.y; az2 += q2.z - c2.z; aw2 += q2.w - c2.w;
            ax3 += q3.x - c3.x; ay3 += q3.y - c3.y; az3 += q3.z - c3.z; aw3 += q3.w - c3.w;
            s = g_next[s - 1];
        }
        float* d = dst + (size_t)c * EMBED;     // misaligned: scalar stores
        int e0 = lane * 4;
        d[e0+0]      = c0.x + ALPHA_C*ax0; d[e0+1]      = c0.y + ALPHA_C*ay0;
        d[e0+2]      = c0.z + ALPHA_C*az0; d[e0+3]      = c0.w + ALPHA_C*aw0;
        d[e0+128+0]  = c1.x + ALPHA_C*ax1; d[e0+128+1]  = c1.y + ALPHA_C*ay1;
        d[e0+128+2]  = c1.z + ALPHA_C*az1; d[e0+128+3]  = c1.w + ALPHA_C*aw1;
        d[e0+256+0]  = c2.x + ALPHA_C*ax2; d[e0+256+1]  = c2.y + ALPHA_C*ay2;
        d[e0+256+2]  = c2.z + ALPHA_C*az2; d[e0+256+3]  = c2.w + ALPHA_C*aw2;
        d[e0+384+0]  = c3.x + ALPHA_C*ax3; d[e0+384+1]  = c3.y + ALPHA_C*ay3;
        d[e0+384+2]  = c3.z + ALPHA_C*az3; d[e0+384+3]  = c3.w + ALPHA_C*aw3;

        if (lane == 0) g_head[c] = 0;           // restore zero-invariant
    }
}

extern "C" void kernel_launch(void* const* d_in, const int* in_sizes, int n_in,
                              void* d_out, int out_size) {
    const int*   y       = (const int*)d_in[0];
    const float* batch   = (const float*)d_in[1];
    const float* centers = (const float*)d_in[2];

    float* out = (float*)d_out;

    float* loss_ptr;
    float* new_centers;
    if (out_size == (int)(NCS + 1)) {
        loss_ptr = out;
        new_centers = out + 1;
    } else {
        new_centers = out;
        loss_ptr = out + NCS;
    }

    // 1) copy at full rate; builds chains + zeroes loss on the side
    copy_build_kernel<<<COPY_GRID, 256>>>(
        reinterpret_cast<const float4*>(centers), new_centers, y, loss_ptr);

    // 2) warp-per-sample fixup + loss; restores g_head zeros
    fixup_kernel<<<BATCH_N / 8, 256>>>(y,
        reinterpret_cast<const float4*>(batch),
        reinterpret_cast<const float4*>(centers),
        new_centers, loss_ptr);
}